// round 1
// baseline (speedup 1.0000x reference)
#include <cuda_runtime.h>
#include <cuda_bf16.h>

// Problem constants (fixed by the reference):
//   B=16, N=4096, K=16, hidden=64, dim=64
//   inputs: xyz[16,4096,3] f32, dist[16,4096,16] f32, W1[10,64] f32, b1[64] f32,
//           W2[64,64] f32, b2[64] f32, idx[16,4096,16] int64-or-int32
//   out: [16,4096,16,64] f32
//
// Restructure:
//   h_pre[m][j] = cgroup[pair(m)][j] + nb.Bm[:,j] + dist[m]*w9[j]
//   out[m][:]   = relu(h_pre[m]) @ W2 + b2
// where A = W1[0:3]+W1[6:9], Bm = W1[3:6]-W1[6:9], w9 = W1[9],
//       cgroup = b1 + center . A  (shared by the K=16 rows of one (b,n) pair).

#define NPAIR_PER_CTA 8          // (b,n) pairs per CTA
#define ROWS_PER_CTA  128        // 8 pairs * K=16 rows
#define THREADS       256

__device__ int g_idx_is64;

// idx dtype sniffing: int64 little-endian with values in [0,4096) has all-zero
// odd 32-bit words; for a genuine int32 buffer the odd positions are random
// indices (all four zero w.p. 4096^-4 ~ 3.5e-15).
__global__ void ppe_detect_idx_kernel(const int* __restrict__ idx32) {
    g_idx_is64 = (idx32[1] == 0 && idx32[3] == 0 && idx32[5] == 0 && idx32[7] == 0) ? 1 : 0;
}

__global__ __launch_bounds__(THREADS)
void ppe_main_kernel(const float* __restrict__ xyz,
                     const float* __restrict__ dist,
                     const float* __restrict__ W1,
                     const float* __restrict__ b1,
                     const float* __restrict__ W2,
                     const float* __restrict__ b2,
                     const void*  __restrict__ idx_raw,
                     float* __restrict__ out)
{
    // 48 KB static shared total (fits the 48 KB static limit exactly).
    __shared__ float4 Uv[1024];   // 16 KB: phase2 = {A, Bm, w9, cgroup}; phase3 = W2
    __shared__ float4 h4[2048];   // 32 KB: h_s[j][r], j=0..63, r=0..127 (r fastest)
    float* U   = reinterpret_cast<float*>(Uv);
    float* h_s = reinterpret_cast<float*>(h4);

    const int t   = threadIdx.x;
    const int cta = blockIdx.x;
    const int p0  = cta * NPAIR_PER_CTA;      // first (b,n) pair index of this CTA
    const int is64 = g_idx_is64;

    // ---------------- setup: A[3][64] @U[0..191], Bm[3][64] @U[192..383], w9 @U[384..447]
    if (t < 192) {
        const int c = t >> 6, j = t & 63;
        const float w_c  = W1[c * 64 + j];
        const float w_c3 = W1[(3 + c) * 64 + j];
        const float w_c6 = W1[(6 + c) * 64 + j];
        U[t]       = w_c  + w_c6;   // A[c][j]
        U[192 + t] = w_c3 - w_c6;   // Bm[c][j]
    } else {
        const int j = t - 192;      // t in [192,256) -> j in [0,64)
        U[384 + j] = W1[9 * 64 + j];
    }
    __syncthreads();

    // ---------------- cgroup[g][j] = b1[j] + center . A   @U[448..959]
    #pragma unroll
    for (int e = t; e < NPAIR_PER_CTA * 64; e += THREADS) {
        const int g = e >> 6, j = e & 63;
        const int p = p0 + g;
        const float cx = xyz[p * 3 + 0];
        const float cy = xyz[p * 3 + 1];
        const float cz = xyz[p * 3 + 2];
        float v = b1[j];
        v = fmaf(cx, U[j],        v);
        v = fmaf(cy, U[64  + j],  v);
        v = fmaf(cz, U[128 + j],  v);
        U[448 + e] = v;
    }
    __syncthreads();

    // ---------------- phase 2: h_s[j][r] = relu(cgroup + nb.Bm + d*w9)
    {
        const int r  = t & 127;          // row within CTA (0..127)
        const int jh = t >> 7;           // 0/1 -> j in [32*jh, 32*jh+32)
        const int m  = cta * ROWS_PER_CTA + r;   // global row
        const int p  = m >> 4;           // (b,n) pair
        const int b  = p >> 12;          // batch

        int nb;
        if (is64) nb = (int)(((const long long*)idx_raw)[m]);
        else      nb = ((const int*)idx_raw)[m];

        const float* nx3 = xyz + ((size_t)((b << 12) + nb)) * 3;
        const float nx = nx3[0], ny = nx3[1], nz = nx3[2];
        const float dd = dist[m];

        const int   g  = r >> 4;
        const float* cg = U + 448 + g * 64;
        const int jbase = jh * 32;

        #pragma unroll
        for (int jj = 0; jj < 32; jj += 4) {
            const int j = jbase + jj;
            const float4 B0v = *(const float4*)(U + 192 + j);
            const float4 B1v = *(const float4*)(U + 256 + j);
            const float4 B2v = *(const float4*)(U + 320 + j);
            const float4 w9v = *(const float4*)(U + 384 + j);
            const float4 cgv = *(const float4*)(cg + j);

            float h0 = fmaf(nx, B0v.x, fmaf(ny, B1v.x, fmaf(nz, B2v.x, fmaf(dd, w9v.x, cgv.x))));
            float h1 = fmaf(nx, B0v.y, fmaf(ny, B1v.y, fmaf(nz, B2v.y, fmaf(dd, w9v.y, cgv.y))));
            float h2 = fmaf(nx, B0v.z, fmaf(ny, B1v.z, fmaf(nz, B2v.z, fmaf(dd, w9v.z, cgv.z))));
            float h3 = fmaf(nx, B0v.w, fmaf(ny, B1v.w, fmaf(nz, B2v.w, fmaf(dd, w9v.w, cgv.w))));

            h_s[(j + 0) * 128 + r] = fmaxf(h0, 0.0f);
            h_s[(j + 1) * 128 + r] = fmaxf(h1, 0.0f);
            h_s[(j + 2) * 128 + r] = fmaxf(h2, 0.0f);
            h_s[(j + 3) * 128 + r] = fmaxf(h3, 0.0f);
        }
    }
    __syncthreads();

    // ---------------- reload U with W2 [64][64] (j-major, d fastest)
    {
        const float4* w2v = (const float4*)W2;
        #pragma unroll
        for (int v = 0; v < 4; v++) Uv[t + v * THREADS] = w2v[t + v * THREADS];
    }
    __syncthreads();

    // ---------------- phase 3: out[128 x 64] = h_s @ W2 (+ b2)
    // thread tile: 4 rows x 8 cols. rowBlk = t/8 (0..31), colBlk = t%8.
    const int colBlk = t & 7;
    const int rowBlk = t >> 3;

    float acc[4][8];
    #pragma unroll
    for (int i = 0; i < 4; i++)
        #pragma unroll
        for (int c = 0; c < 8; c++) acc[i][c] = 0.0f;

    #pragma unroll 8
    for (int j = 0; j < 64; ++j) {
        const float4 hv  = h4[j * 32 + rowBlk];                  // rows 4*rowBlk..+3
        const float4 wv0 = Uv[j * 16 + (colBlk << 1)];           // cols 8*colBlk..+3
        const float4 wv1 = Uv[j * 16 + (colBlk << 1) + 1];       // cols 8*colBlk+4..+7
        const float a[4] = {hv.x, hv.y, hv.z, hv.w};
        const float w[8] = {wv0.x, wv0.y, wv0.z, wv0.w, wv1.x, wv1.y, wv1.z, wv1.w};
        #pragma unroll
        for (int i = 0; i < 4; ++i)
            #pragma unroll
            for (int c = 0; c < 8; ++c)
                acc[i][c] = fmaf(a[i], w[c], acc[i][c]);
    }

    // epilogue: + b2, fully coalesced float4 stores (each thread owns 32B sectors)
    float bb[8];
    #pragma unroll
    for (int c = 0; c < 8; c++) bb[c] = b2[colBlk * 8 + c];

    #pragma unroll
    for (int i = 0; i < 4; ++i) {
        const size_t m = (size_t)cta * ROWS_PER_CTA + rowBlk * 4 + i;
        float* o = out + m * 64 + colBlk * 8;
        float4 o0, o1;
        o0.x = acc[i][0] + bb[0]; o0.y = acc[i][1] + bb[1];
        o0.z = acc[i][2] + bb[2]; o0.w = acc[i][3] + bb[3];
        o1.x = acc[i][4] + bb[4]; o1.y = acc[i][5] + bb[5];
        o1.z = acc[i][6] + bb[6]; o1.w = acc[i][7] + bb[7];
        *(float4*)(o)     = o0;
        *(float4*)(o + 4) = o1;
    }
}

extern "C" void kernel_launch(void* const* d_in, const int* in_sizes, int n_in,
                              void* d_out, int out_size)
{
    const float* xyz  = (const float*)d_in[0];   // [16,4096,3]
    const float* dist = (const float*)d_in[1];   // [16,4096,16]
    const float* W1   = (const float*)d_in[2];   // [10,64]
    const float* b1   = (const float*)d_in[3];   // [64]
    const float* W2   = (const float*)d_in[4];   // [64,64]
    const float* b2   = (const float*)d_in[5];   // [64]
    const void*  idx  = d_in[6];                 // [16,4096,16] int64 or int32
    float* out = (float*)d_out;                  // [16,4096,16,64]

    ppe_detect_idx_kernel<<<1, 1>>>((const int*)idx);

    const int total_rows = 16 * 4096 * 16;               // 1048576
    const int grid = total_rows / ROWS_PER_CTA;          // 8192
    ppe_main_kernel<<<grid, THREADS>>>(xyz, dist, W1, b1, W2, b2, idx, out);
}

// round 3
// speedup vs baseline: 1.5286x; 1.5286x over previous
#include <cuda_runtime.h>
#include <cuda_bf16.h>

// B=16, N=4096, K=16, hidden=64, dim=64.
//   out[m] = relu(h_pre[m]) @ W2 + b2,   m = 0..1048575 rows
//   h_pre[m][j] = cgroup[pair(m)][j] + nb.Bm[:,j] + dist[m]*w9[j]
//   A = W1[0:3]+W1[6:9], Bm = W1[3:6]-W1[6:9], w9 = W1[9]
//   cgroup = b1 + center . A  (shared by the K=16 rows of a (b,n) pair)
//
// Round-2 changes vs round 1 (L1=96% bound, fma=37%):
//   * 128 threads/CTA, 8x8 per-thread output tile -> 1.0 B smem per lane-FMA
//   * packed fma.rn.f32x2 -> half the FMA instruction stream
//   * W2 column-pairs taken directly from float4 LDS (no packing insts);
//     only h row-broadcast needs mov.b64 {a,a} dups (8 per 128 lane-FMA)

#define NPAIR_PER_CTA 8
#define ROWS_PER_CTA  128
#define THREADS       128

typedef unsigned long long u64;

__device__ int g_idx_is64;

// int64 little-endian with values in [0,4096): odd 32-bit words are all zero.
__global__ void ppe_detect_idx_kernel(const int* __restrict__ idx32) {
    g_idx_is64 = (idx32[1] == 0 && idx32[3] == 0 && idx32[5] == 0 && idx32[7] == 0) ? 1 : 0;
}

__device__ __forceinline__ u64 pack_dup(float a) {
    u64 r;
    asm("mov.b64 %0, {%1, %1};" : "=l"(r) : "r"(__float_as_uint(a)));
    return r;
}
__device__ __forceinline__ u64 pack2(float lo, float hi) {
    u64 r;
    asm("mov.b64 %0, {%1, %2};" : "=l"(r) : "r"(__float_as_uint(lo)), "r"(__float_as_uint(hi)));
    return r;
}
__device__ __forceinline__ void fma2(u64& d, u64 a, u64 b) {
    asm("fma.rn.f32x2 %0, %1, %2, %0;" : "+l"(d) : "l"(a), "l"(b));
}
__device__ __forceinline__ u64 add2(u64 a, u64 b) {
    u64 d;
    asm("add.rn.f32x2 %0, %1, %2;" : "=l"(d) : "l"(a), "l"(b));
    return d;
}

__global__ __launch_bounds__(THREADS, 4)
void ppe_main_kernel(const float* __restrict__ xyz,
                     const float* __restrict__ dist,
                     const float* __restrict__ W1,
                     const float* __restrict__ b1,
                     const float* __restrict__ W2,
                     const float* __restrict__ b2,
                     const void*  __restrict__ idx_raw,
                     float* __restrict__ out)
{
    // 48 KB static shared
    __shared__ float4 Uv[1024];   // 16 KB: phase2 = {A, Bm, w9, cgroup}; phase3 = W2 [j][d]
    __shared__ float4 h4[2048];   // 32 KB: h_s[j][r], j=0..63, r=0..127 (r fastest)
    float* U = reinterpret_cast<float*>(Uv);
    float* h_s = reinterpret_cast<float*>(h4);

    const int t    = threadIdx.x;
    const int cta  = blockIdx.x;
    const int p0   = cta * NPAIR_PER_CTA;
    const int is64 = g_idx_is64;

    // ---- setup: A[3][64] @U[0..191], Bm[3][64] @U[192..383], w9 @U[384..447]
    #pragma unroll
    for (int e = t; e < 192; e += THREADS) {
        const int c = e >> 6, j = e & 63;
        const float w_c  = W1[c * 64 + j];
        const float w_c3 = W1[(3 + c) * 64 + j];
        const float w_c6 = W1[(6 + c) * 64 + j];
        U[e]       = w_c  + w_c6;
        U[192 + e] = w_c3 - w_c6;
    }
    if (t < 64) U[384 + t] = W1[576 + t];
    __syncthreads();

    // ---- cgroup[g][j] = b1[j] + center . A   @U[448..959]
    #pragma unroll
    for (int e = t; e < NPAIR_PER_CTA * 64; e += THREADS) {
        const int g = e >> 6, j = e & 63;
        const int p = p0 + g;
        const float cx = xyz[p * 3 + 0];
        const float cy = xyz[p * 3 + 1];
        const float cz = xyz[p * 3 + 2];
        float v = b1[j];
        v = fmaf(cx, U[j],        v);
        v = fmaf(cy, U[64  + j],  v);
        v = fmaf(cz, U[128 + j],  v);
        U[448 + e] = v;
    }
    __syncthreads();

    // ---- phase 2: each thread computes one full row (all 64 j)
    {
        const int r = t;
        const int m = cta * ROWS_PER_CTA + r;
        const int p = m >> 4;
        const int b = p >> 12;

        int nb;
        if (is64) nb = (int)(((const long long*)idx_raw)[m]);
        else      nb = ((const int*)idx_raw)[m];

        const float* nx3 = xyz + ((size_t)((b << 12) + nb)) * 3;
        const float nx = nx3[0], ny = nx3[1], nz = nx3[2];
        const float dd = dist[m];
        const float* cg = U + 448 + ((r >> 4) << 6);

        #pragma unroll 8
        for (int j = 0; j < 64; j += 4) {
            const float4 B0v = *(const float4*)(U + 192 + j);
            const float4 B1v = *(const float4*)(U + 256 + j);
            const float4 B2v = *(const float4*)(U + 320 + j);
            const float4 w9v = *(const float4*)(U + 384 + j);
            const float4 cgv = *(const float4*)(cg + j);

            float h0 = fmaf(nx, B0v.x, fmaf(ny, B1v.x, fmaf(nz, B2v.x, fmaf(dd, w9v.x, cgv.x))));
            float h1 = fmaf(nx, B0v.y, fmaf(ny, B1v.y, fmaf(nz, B2v.y, fmaf(dd, w9v.y, cgv.y))));
            float h2 = fmaf(nx, B0v.z, fmaf(ny, B1v.z, fmaf(nz, B2v.z, fmaf(dd, w9v.z, cgv.z))));
            float h3 = fmaf(nx, B0v.w, fmaf(ny, B1v.w, fmaf(nz, B2v.w, fmaf(dd, w9v.w, cgv.w))));

            h_s[(j + 0) * 128 + r] = fmaxf(h0, 0.0f);
            h_s[(j + 1) * 128 + r] = fmaxf(h1, 0.0f);
            h_s[(j + 2) * 128 + r] = fmaxf(h2, 0.0f);
            h_s[(j + 3) * 128 + r] = fmaxf(h3, 0.0f);
        }
    }
    __syncthreads();

    // ---- reload U with W2 [64][64] (j-major, d fastest)
    {
        const float4* w2v = (const float4*)W2;
        #pragma unroll
        for (int v = 0; v < 8; v++) Uv[t + v * THREADS] = w2v[t + v * THREADS];
    }
    __syncthreads();

    // ---- phase 3: out[128 x 64] = h_s @ W2 (+ b2), 8x8 per-thread, f32x2 packed
    const int colBlk = t & 7;        // 8 col-blocks of 8 cols
    const int rowBlk = t >> 3;       // 16 row-blocks of 8 rows

    u64 acc[8][4];                   // 8 rows x 4 col-pairs
    #pragma unroll
    for (int i = 0; i < 8; i++)
        #pragma unroll
        for (int c = 0; c < 4; c++) acc[i][c] = 0ULL;

    #pragma unroll 8
    for (int j = 0; j < 64; ++j) {
        const float4 hv0 = h4[j * 32 + (rowBlk << 1)];        // rows 8rb..8rb+3
        const float4 hv1 = h4[j * 32 + (rowBlk << 1) + 1];    // rows 8rb+4..+7
        const ulonglong2 wp0 = *reinterpret_cast<const ulonglong2*>(&Uv[j * 16 + (colBlk << 1)]);
        const ulonglong2 wp1 = *reinterpret_cast<const ulonglong2*>(&Uv[j * 16 + (colBlk << 1) + 1]);
        const float hr[8] = {hv0.x, hv0.y, hv0.z, hv0.w, hv1.x, hv1.y, hv1.z, hv1.w};
        #pragma unroll
        for (int i = 0; i < 8; ++i) {
            const u64 aa = pack_dup(hr[i]);
            fma2(acc[i][0], aa, wp0.x);
            fma2(acc[i][1], aa, wp0.y);
            fma2(acc[i][2], aa, wp1.x);
            fma2(acc[i][3], aa, wp1.y);
        }
    }

    // ---- epilogue: +b2 (packed), coalesced 16B stores
    const float4 b2v0 = *(const float4*)(b2 + (colBlk << 3));
    const float4 b2v1 = *(const float4*)(b2 + (colBlk << 3) + 4);
    const u64 bb0 = pack2(b2v0.x, b2v0.y);
    const u64 bb1 = pack2(b2v0.z, b2v0.w);
    const u64 bb2 = pack2(b2v1.x, b2v1.y);
    const u64 bb3 = pack2(b2v1.z, b2v1.w);

    #pragma unroll
    for (int i = 0; i < 8; ++i) {
        const size_t m = (size_t)cta * ROWS_PER_CTA + (rowBlk << 3) + i;
        float* o = out + m * 64 + (colBlk << 3);
        ulonglong2 s0, s1;
        s0.x = add2(acc[i][0], bb0);
        s0.y = add2(acc[i][1], bb1);
        s1.x = add2(acc[i][2], bb2);
        s1.y = add2(acc[i][3], bb3);
        *reinterpret_cast<ulonglong2*>(o)     = s0;
        *reinterpret_cast<ulonglong2*>(o + 4) = s1;
    }
}

extern "C" void kernel_launch(void* const* d_in, const int* in_sizes, int n_in,
                              void* d_out, int out_size)
{
    const float* xyz  = (const float*)d_in[0];   // [16,4096,3]
    const float* dist = (const float*)d_in[1];   // [16,4096,16]
    const float* W1   = (const float*)d_in[2];   // [10,64]
    const float* b1   = (const float*)d_in[3];   // [64]
    const float* W2   = (const float*)d_in[4];   // [64,64]
    const float* b2   = (const float*)d_in[5];   // [64]
    const void*  idx  = d_in[6];                 // [16,4096,16] int64 or int32
    float* out = (float*)d_out;                  // [16,4096,16,64]

    ppe_detect_idx_kernel<<<1, 1>>>((const int*)idx);

    const int total_rows = 16 * 4096 * 16;               // 1048576
    const int grid = total_rows / ROWS_PER_CTA;          // 8192
    ppe_main_kernel<<<grid, THREADS>>>(xyz, dist, W1, b1, W2, b2, idx, out);
}